// round 14
// baseline (speedup 1.0000x reference)
#include <cuda_runtime.h>

// FuzzyARTMAP single fused kernel: match scores + row sums + argmax.
// N=1024, D=256, C=512, fp32. match[n,c] = sum_d min(x,w) / sum_d x; gate 0.75;
// first-occurrence argmax.
//
// R14: w-stationary, barrier-free mainloop. Each block stores its 64 w-rows x
// full D=256 in smem ONCE (66.5KB dynamic, single __syncthreads), and reads x
// straight from global: broadcast LDG (1 addr / 16 lanes), L1-resident after the
// xsum pass prewarms the 64KB x strip. Steady state = 64 chunks of 4x4 min-plus
// with NO block synchronization — eliminating the LDG->STS->bar->LDS phase
// machinery that every smem-x variant (R3-R13) shared while pinned at ~21us.

#define N_ROWS 1024
#define D_DIM  256
#define C_CATS 512
#define VIG    0.75f

#define BM 64
#define BN 64
#define NCB (C_CATS / BN)     // column-blocks per row = 8
#define WSTRIDE 260           // w row stride (floats): 1040B, 16B-aligned, conflict-free

__device__ unsigned long long g_key[N_ROWS];   // zero at load; self-reset each launch
__device__ unsigned int       g_cnt[N_ROWS];   // zero at load; self-reset each launch

static const int SMEM_BYTES = BN * WSTRIDE * 4;   // 66560 B

// ---------------------------------------------------------------------------
__global__ __launch_bounds__(256) void fused_kernel(const float* __restrict__ x,
                                                    const float* __restrict__ w,
                                                    float* __restrict__ out,
                                                    float* __restrict__ idx_out) {
    extern __shared__ float Bs[];                 // [BN][WSTRIDE] w strip
    __shared__ float xq[BM][4];                   // per-row quarter sums of x
    __shared__ unsigned long long skey[BM];       // per-row best (val, col) key

    const int t  = threadIdx.x;
    const int tx = t & 15;        // 16 thread-columns
    const int ty = t >> 4;        // 16 thread-rows (4 rows each)
    const int rowBase = blockIdx.y * BM;
    const int colBase = blockIdx.x * BN;

    if (t < BM) skey[t] = 0ull;

    // ---- Load the whole 64x256 w strip into smem (16 float4 per thread) ----
    #pragma unroll
    for (int i = 0; i < 16; i++) {
        int idx = t + 256 * i;          // 0..4095
        int r   = idx >> 6;             // w row (64 float4 per row)
        int c4  = idx & 63;             // float4 col
        *(float4*)&Bs[r * WSTRIDE + 4 * c4] =
            *(const float4*)(w + (size_t)(colBase + r) * D_DIM + 4 * c4);
    }

    // ---- x row sums from GLOBAL (independent of smem; prewarms x into L1) ----
    {
        const int xr_ = t >> 2;                   // 0..63
        const int xc_ = (t & 3) * 64;             // quarter of D
        const float* rp = x + (size_t)(rowBase + xr_) * D_DIM + xc_;
        float s = 0.f;
        #pragma unroll
        for (int u = 0; u < 16; u++) {
            float4 v = *(const float4*)(rp + 4 * u);
            s += (v.x + v.y) + (v.z + v.w);
        }
        xq[xr_][t & 3] = s;
    }
    __syncthreads();               // the ONLY barrier before the epilogue

    // ---- Barrier-free mainloop: 64 chunks of 4x4 min-plus ----
    float acc[4][4];
    #pragma unroll
    for (int i = 0; i < 4; i++)
        #pragma unroll
        for (int j = 0; j < 4; j++) acc[i][j] = 0.f;

    const float* xr0 = x + (size_t)(rowBase + 4 * ty + 0) * D_DIM;
    const float* xr1 = x + (size_t)(rowBase + 4 * ty + 1) * D_DIM;
    const float* xr2 = x + (size_t)(rowBase + 4 * ty + 2) * D_DIM;
    const float* xr3 = x + (size_t)(rowBase + 4 * ty + 3) * D_DIM;
    const float* b0p = Bs + (tx +  0) * WSTRIDE;
    const float* b1p = Bs + (tx + 16) * WSTRIDE;
    const float* b2p = Bs + (tx + 32) * WSTRIDE;
    const float* b3p = Bs + (tx + 48) * WSTRIDE;

    #pragma unroll 4
    for (int k = 0; k < D_DIM; k += 4) {
        float4 a0 = *(const float4*)(xr0 + k);    // broadcast LDG (1 addr / 16 lanes)
        float4 a1 = *(const float4*)(xr1 + k);
        float4 a2 = *(const float4*)(xr2 + k);
        float4 a3 = *(const float4*)(xr3 + k);
        float4 b0 = *(const float4*)(b0p + k);    // conflict-free LDS.128
        float4 b1 = *(const float4*)(b1p + k);
        float4 b2 = *(const float4*)(b2p + k);
        float4 b3 = *(const float4*)(b3p + k);

        #define STEP(F)                                \
            acc[0][0] += fminf(a0.F, b0.F);           \
            acc[0][1] += fminf(a0.F, b1.F);           \
            acc[0][2] += fminf(a0.F, b2.F);           \
            acc[0][3] += fminf(a0.F, b3.F);           \
            acc[1][0] += fminf(a1.F, b0.F);           \
            acc[1][1] += fminf(a1.F, b1.F);           \
            acc[1][2] += fminf(a1.F, b2.F);           \
            acc[1][3] += fminf(a1.F, b3.F);           \
            acc[2][0] += fminf(a2.F, b0.F);           \
            acc[2][1] += fminf(a2.F, b1.F);           \
            acc[2][2] += fminf(a2.F, b2.F);           \
            acc[2][3] += fminf(a2.F, b3.F);           \
            acc[3][0] += fminf(a3.F, b0.F);           \
            acc[3][1] += fminf(a3.F, b1.F);           \
            acc[3][2] += fminf(a3.F, b2.F);           \
            acc[3][3] += fminf(a3.F, b3.F);
        STEP(x) STEP(y) STEP(z) STEP(w)
        #undef STEP
    }

    // ---- Epilogue: divide, gate, store, per-row argmax key ----
    #pragma unroll
    for (int i = 0; i < 4; i++) {
        int r = 4 * ty + i;
        int n = rowBase + r;
        float xs = (xq[r][0] + xq[r][1]) + (xq[r][2] + xq[r][3]);
        unsigned long long bk = 0ull;
        #pragma unroll
        for (int j = 0; j < 4; j++) {
            int c = colBase + tx + 16 * j;
            float m = acc[i][j] / xs;                  // exact division, as reference
            float g = (m >= VIG) ? m : 0.f;
            out[(size_t)n * C_CATS + c] = g;
            // order-preserving key: larger value wins; ties -> smaller column
            unsigned long long key =
                ((unsigned long long)__float_as_uint(g) << 32) |
                (unsigned long long)(unsigned)(C_CATS - 1 - c);
            if (key > bk) bk = key;
        }
        atomicMax(&skey[r], bk);
    }
    __syncthreads();

    // ---- Cross-block argmax finalization (threadfence reduction, 8 col-blocks) ----
    if (t < BM) {
        int n = rowBase + t;
        atomicMax(&g_key[n], skey[t]);
        __threadfence();
        unsigned old = atomicAdd(&g_cnt[n], 1u);
        if (old == NCB - 1) {                              // last column-block for this row
            __threadfence();
            unsigned long long k = atomicMax(&g_key[n], 0ull);   // atomic read
            if (idx_out)
                idx_out[n] = (float)(C_CATS - 1 - (unsigned)(k & 0xffffffffull));
            g_key[n] = 0ull;                               // self-clean for next replay
            g_cnt[n] = 0u;
        }
    }
}

// ---------------------------------------------------------------------------
extern "C" void kernel_launch(void* const* d_in, const int* in_sizes, int n_in,
                              void* d_out, int out_size) {
    const float* x = (const float*)d_in[0];
    const float* w = (const float*)d_in[1];
    float* out = (float*)d_out;

    static int smem_set = 0;
    if (!smem_set) {
        cudaFuncSetAttribute(fused_kernel,
                             cudaFuncAttributeMaxDynamicSharedMemorySize, SMEM_BYTES);
        smem_set = 1;
    }

    float* idx_out = (out_size >= N_ROWS * C_CATS + N_ROWS)
                   ? out + (size_t)N_ROWS * C_CATS : nullptr;

    dim3 grid(C_CATS / BN, N_ROWS / BM);   // (8, 16) = 128 blocks
    fused_kernel<<<grid, 256, SMEM_BYTES>>>(x, w, out, idx_out);
}

// round 16
// speedup vs baseline: 1.0935x; 1.0935x over previous
#include <cuda_runtime.h>

// FuzzyARTMAP single fused kernel: match scores + row sums + argmax.
// N=1024, D=256, C=512, fp32. match[n,c] = sum_d min(x,w) / sum_d x; gate 0.75;
// first-occurrence argmax.
//
// FINAL: best measured configuration (R9, 20.96us). 512 threads = two 256-thread
// k-halves, each a 4x4 micro-tile over a 32-wide k slice (in-block split-K).
// Fused x row-sums; halves combine via smem; argmax finalized in-kernel via
// threadfence reduction; state arrays self-reset each launch (graph-replay safe).
// 15-round elimination matrix found ~21us to be the floor for this workload:
// occupancy/ILP/instr-count/barriers/grid/regs/residency all perf-neutral, and
// packed f32 min does not exist on sm_103a (ptxas-verified).

#define N_ROWS 1024
#define D_DIM  256
#define C_CATS 512
#define VIG    0.75f

#define BM 64
#define BN 64
#define BK 64
#define NCB (C_CATS / BN)     // column-blocks per row = 8
#define LSTRIDE 68            // 16B-aligned rows; conflict-free per 8-lane LDS.128 phase

__device__ unsigned long long g_key[N_ROWS];   // zero at load; self-reset each launch
__device__ unsigned int       g_cnt[N_ROWS];   // zero at load; self-reset each launch

// ---------------------------------------------------------------------------
__global__ __launch_bounds__(512) void fused_kernel(const float* __restrict__ x,
                                                    const float* __restrict__ w,
                                                    float* __restrict__ out,
                                                    float* __restrict__ idx_out) {
    __shared__ float As[BM][LSTRIDE];             // x tile [m][k]
    __shared__ float Bs[BN][LSTRIDE];             // w tile [c][k]
    __shared__ float xq[BM][8];                   // per-row 1/8 sums of x
    __shared__ unsigned long long skey[BM];       // per-row best (val, col) key

    const int t   = threadIdx.x;
    const int kh  = t >> 8;        // k-half: 0 or 1
    const int tt  = t & 255;       // id within half
    const int tx  = tt & 15;       // 16 thread-columns
    const int ty  = tt >> 4;       // 16 thread-rows (4 rows each)
    const int rowBase = blockIdx.y * BM;
    const int colBase = blockIdx.x * BN;
    const int kbase   = kh * (BK / 2);

    float acc[4][4];
    #pragma unroll
    for (int i = 0; i < 4; i++)
        #pragma unroll
        for (int j = 0; j < 4; j++) acc[i][j] = 0.f;

    float xpart = 0.f;             // x row-sum duty: 8 threads per row, 8 elems each
    const int xr = t >> 3;
    const int xc = (t & 7) * 8;

    if (t < BM) skey[t] = 0ull;

    for (int k0 = 0; k0 < D_DIM; k0 += BK) {
        // Load 64x64 tiles: 1024 float4 per array, 2 per thread.
        #pragma unroll
        for (int i = 0; i < 2; i++) {
            int idx = t + 512 * i;
            int r   = idx >> 4;
            int c4  = idx & 15;
            *(float4*)&As[r][4 * c4] =
                *(const float4*)(x + (size_t)(rowBase + r) * D_DIM + k0 + 4 * c4);
            *(float4*)&Bs[r][4 * c4] =
                *(const float4*)(w + (size_t)(colBase + r) * D_DIM + k0 + 4 * c4);
        }
        __syncthreads();

        // Fused row-sum: each thread sums an 8-wide slice of one As row.
        {
            float4 v0 = *(const float4*)&As[xr][xc];
            float4 v1 = *(const float4*)&As[xr][xc + 4];
            xpart += (v0.x + v0.y) + (v0.z + v0.w) + (v1.x + v1.y) + (v1.z + v1.w);
        }

        // This half processes k in [kbase, kbase+32) with the 4x4 core.
        #pragma unroll
        for (int kk = 0; kk < BK / 2; kk += 4) {
            const int k = kbase + kk;
            float4 a0 = *(const float4*)&As[4 * ty + 0][k];
            float4 a1 = *(const float4*)&As[4 * ty + 1][k];
            float4 a2 = *(const float4*)&As[4 * ty + 2][k];
            float4 a3 = *(const float4*)&As[4 * ty + 3][k];
            float4 b0 = *(const float4*)&Bs[tx +  0][k];
            float4 b1 = *(const float4*)&Bs[tx + 16][k];
            float4 b2 = *(const float4*)&Bs[tx + 32][k];
            float4 b3 = *(const float4*)&Bs[tx + 48][k];

            #define STEP(F)                                \
                acc[0][0] += fminf(a0.F, b0.F);           \
                acc[0][1] += fminf(a0.F, b1.F);           \
                acc[0][2] += fminf(a0.F, b2.F);           \
                acc[0][3] += fminf(a0.F, b3.F);           \
                acc[1][0] += fminf(a1.F, b0.F);           \
                acc[1][1] += fminf(a1.F, b1.F);           \
                acc[1][2] += fminf(a1.F, b2.F);           \
                acc[1][3] += fminf(a1.F, b3.F);           \
                acc[2][0] += fminf(a2.F, b0.F);           \
                acc[2][1] += fminf(a2.F, b1.F);           \
                acc[2][2] += fminf(a2.F, b2.F);           \
                acc[2][3] += fminf(a2.F, b3.F);           \
                acc[3][0] += fminf(a3.F, b0.F);           \
                acc[3][1] += fminf(a3.F, b1.F);           \
                acc[3][2] += fminf(a3.F, b2.F);           \
                acc[3][3] += fminf(a3.F, b3.F);
            STEP(x) STEP(y) STEP(z) STEP(w)
            #undef STEP
        }
        __syncthreads();
    }

    // Publish x row-sum slices.
    xq[t >> 3][t & 7] = xpart;

    // Combine k-halves: kh=1 stages its 16 partials in the (now dead) As region.
    float* stage = &As[0][0];                     // 256 threads x 16 floats = 16KB <= As
    if (kh) {
        #pragma unroll
        for (int i = 0; i < 4; i++)
            *(float4*)&stage[tt * 16 + 4 * i] =
                make_float4(acc[i][0], acc[i][1], acc[i][2], acc[i][3]);
    }
    __syncthreads();

    if (!kh) {
        #pragma unroll
        for (int i = 0; i < 4; i++) {
            float4 p = *(const float4*)&stage[tt * 16 + 4 * i];
            acc[i][0] += p.x; acc[i][1] += p.y; acc[i][2] += p.z; acc[i][3] += p.w;
        }

        // Epilogue: divide, gate, store, per-row argmax key.
        #pragma unroll
        for (int i = 0; i < 4; i++) {
            int r = 4 * ty + i;
            int n = rowBase + r;
            float xs = ((xq[r][0] + xq[r][1]) + (xq[r][2] + xq[r][3]))
                     + ((xq[r][4] + xq[r][5]) + (xq[r][6] + xq[r][7]));
            unsigned long long bk = 0ull;
            #pragma unroll
            for (int j = 0; j < 4; j++) {
                int c = colBase + tx + 16 * j;
                float m = acc[i][j] / xs;                  // exact division, as reference
                float g = (m >= VIG) ? m : 0.f;
                out[(size_t)n * C_CATS + c] = g;
                // order-preserving key: larger value wins; ties -> smaller column
                unsigned long long key =
                    ((unsigned long long)__float_as_uint(g) << 32) |
                    (unsigned long long)(unsigned)(C_CATS - 1 - c);
                if (key > bk) bk = key;
            }
            atomicMax(&skey[r], bk);
        }
    }
    __syncthreads();

    // Cross-block argmax finalization (threadfence reduction over 8 col-blocks).
    if (t < BM) {
        int n = rowBase + t;
        atomicMax(&g_key[n], skey[t]);
        __threadfence();
        unsigned old = atomicAdd(&g_cnt[n], 1u);
        if (old == NCB - 1) {                              // last column-block for this row
            __threadfence();
            unsigned long long k = atomicMax(&g_key[n], 0ull);   // atomic read
            if (idx_out)
                idx_out[n] = (float)(C_CATS - 1 - (unsigned)(k & 0xffffffffull));
            g_key[n] = 0ull;                               // self-clean for next replay
            g_cnt[n] = 0u;
        }
    }
}

// ---------------------------------------------------------------------------
extern "C" void kernel_launch(void* const* d_in, const int* in_sizes, int n_in,
                              void* d_out, int out_size) {
    const float* x = (const float*)d_in[0];
    const float* w = (const float*)d_in[1];
    float* out = (float*)d_out;

    float* idx_out = (out_size >= N_ROWS * C_CATS + N_ROWS)
                   ? out + (size_t)N_ROWS * C_CATS : nullptr;

    dim3 grid(C_CATS / BN, N_ROWS / BM);   // (8, 16) = 128 blocks
    fused_kernel<<<grid, 512>>>(x, w, out, idx_out);
}

// round 17
// speedup vs baseline: 1.2137x; 1.1099x over previous
#include <cuda_runtime.h>

// FuzzyARTMAP single fused kernel: match scores + row sums + argmax.
// N=1024, D=256, C=512, fp32. match[n,c] = sum_d min(x,w) / sum_d x; gate 0.75;
// first-occurrence argmax.
//
// FINAL (R13 config — best measured ncu kernel duration, 20.64us): 256 threads,
// 4x4 micro-tile, float4 LDS, BM=BN=BK=64, direct LDG->STS (no prefetch), small
// unrolled body, fused x row-sums, in-kernel argmax finalization. Accumulation
// uses fmaf(min, 1.0f, acc) -> FFMA-imm (rt 1 on sm_103a, vs FADD rt 2): exact
// same arithmetic (min*1+acc), half the fma-pipe reciprocal-throughput cost.
// 16-round study: workload plateaus at ~21.3us +/- ~1.2us run-to-run; occupancy,
// ILP, instr count, barriers, grid size, regs, residency all within noise, and
// packed f32 min does not exist in the sm_103a PTX ISA (ptxas-verified).

#define N_ROWS 1024
#define D_DIM  256
#define C_CATS 512
#define VIG    0.75f

#define BM 64
#define BN 64
#define BK 64
#define NCB (C_CATS / BN)     // column-blocks per row = 8
#define LSTRIDE 68            // 16B-aligned rows; conflict-free LDS.128 phases

__device__ unsigned long long g_key[N_ROWS];   // zero at load; self-reset each launch
__device__ unsigned int       g_cnt[N_ROWS];   // zero at load; self-reset each launch

// ---------------------------------------------------------------------------
__global__ __launch_bounds__(256) void fused_kernel(const float* __restrict__ x,
                                                    const float* __restrict__ w,
                                                    float* __restrict__ out,
                                                    float* __restrict__ idx_out) {
    __shared__ float As[BM][LSTRIDE];             // x tile [m][k]
    __shared__ float Bs[BN][LSTRIDE];             // w tile [c][k]
    __shared__ float xq[BM][4];                   // per-row quarter sums of x
    __shared__ unsigned long long skey[BM];       // per-row best (val, col) key

    const int t  = threadIdx.x;
    const int tx = t & 15;        // 16 thread-columns
    const int ty = t >> 4;        // 16 thread-rows (4 rows each)
    const int rowBase = blockIdx.y * BM;
    const int colBase = blockIdx.x * BN;

    float acc[4][4];
    #pragma unroll
    for (int i = 0; i < 4; i++)
        #pragma unroll
        for (int j = 0; j < 4; j++) acc[i][j] = 0.f;

    float xpart = 0.f;             // x row-sum duty: 4 threads per row, 16 elems each
    const int xr = t >> 2;
    const int xc = (t & 3) * 16;

    if (t < BM) skey[t] = 0ull;

    // Tile-load mapping: 4 float4 per array per thread (rows lr+16i).
    const int lr = t >> 4;        // 0..15
    const int lc = t & 15;        // float4 column (BK/4 = 16)

    for (int k0 = 0; k0 < D_DIM; k0 += BK) {
        // Direct LDG -> STS (no register prefetch: keeps live regs low).
        #pragma unroll
        for (int i = 0; i < 4; i++) {
            int r = lr + 16 * i;
            *(float4*)&As[r][4 * lc] =
                *(const float4*)(x + (size_t)(rowBase + r) * D_DIM + k0 + 4 * lc);
            *(float4*)&Bs[r][4 * lc] =
                *(const float4*)(w + (size_t)(colBase + r) * D_DIM + k0 + 4 * lc);
        }
        __syncthreads();

        // Fused row-sum: each thread sums a 16-wide quarter of one As row.
        {
            const float* rp = &As[xr][xc];
            float s = 0.f;
            #pragma unroll
            for (int u = 0; u < 4; u++) {
                float4 v = *(const float4*)(rp + 4 * u);
                s += (v.x + v.y) + (v.z + v.w);
            }
            xpart += s;
        }

        // Small body: unroll 4 chunks of 4k (fits L0 I$).
        // acc += min via FFMA-imm (rt 1): fmaf(min, 1.0f, acc) == min + acc exactly.
        #pragma unroll 4
        for (int k = 0; k < BK; k += 4) {
            float4 a0 = *(const float4*)&As[4 * ty + 0][k];
            float4 a1 = *(const float4*)&As[4 * ty + 1][k];
            float4 a2 = *(const float4*)&As[4 * ty + 2][k];
            float4 a3 = *(const float4*)&As[4 * ty + 3][k];
            float4 b0 = *(const float4*)&Bs[tx +  0][k];
            float4 b1 = *(const float4*)&Bs[tx + 16][k];
            float4 b2 = *(const float4*)&Bs[tx + 32][k];
            float4 b3 = *(const float4*)&Bs[tx + 48][k];

            #define ACC(I, J, AV, BV) acc[I][J] = fmaf(fminf(AV, BV), 1.0f, acc[I][J])
            #define STEP(F)                     \
                ACC(0, 0, a0.F, b0.F);          \
                ACC(0, 1, a0.F, b1.F);          \
                ACC(0, 2, a0.F, b2.F);          \
                ACC(0, 3, a0.F, b3.F);          \
                ACC(1, 0, a1.F, b0.F);          \
                ACC(1, 1, a1.F, b1.F);          \
                ACC(1, 2, a1.F, b2.F);          \
                ACC(1, 3, a1.F, b3.F);          \
                ACC(2, 0, a2.F, b0.F);          \
                ACC(2, 1, a2.F, b1.F);          \
                ACC(2, 2, a2.F, b2.F);          \
                ACC(2, 3, a2.F, b3.F);          \
                ACC(3, 0, a3.F, b0.F);          \
                ACC(3, 1, a3.F, b1.F);          \
                ACC(3, 2, a3.F, b2.F);          \
                ACC(3, 3, a3.F, b3.F);
            STEP(x) STEP(y) STEP(z) STEP(w)
            #undef STEP
            #undef ACC
        }
        __syncthreads();
    }

    xq[xr][t & 3] = xpart;
    __syncthreads();

    // Epilogue: divide, gate, store, per-row argmax key.
    #pragma unroll
    for (int i = 0; i < 4; i++) {
        int r = 4 * ty + i;
        int n = rowBase + r;
        float xs = (xq[r][0] + xq[r][1]) + (xq[r][2] + xq[r][3]);
        unsigned long long bk = 0ull;
        #pragma unroll
        for (int j = 0; j < 4; j++) {
            int c = colBase + tx + 16 * j;
            float m = acc[i][j] / xs;                  // exact division, as reference
            float g = (m >= VIG) ? m : 0.f;
            out[(size_t)n * C_CATS + c] = g;
            // order-preserving key: larger value wins; ties -> smaller column
            unsigned long long key =
                ((unsigned long long)__float_as_uint(g) << 32) |
                (unsigned long long)(unsigned)(C_CATS - 1 - c);
            if (key > bk) bk = key;
        }
        atomicMax(&skey[r], bk);
    }
    __syncthreads();

    // Cross-block argmax finalization (threadfence reduction over 8 col-blocks).
    if (t < BM) {
        int n = rowBase + t;
        atomicMax(&g_key[n], skey[t]);
        __threadfence();
        unsigned old = atomicAdd(&g_cnt[n], 1u);
        if (old == NCB - 1) {                              // last column-block for this row
            __threadfence();
            unsigned long long k = atomicMax(&g_key[n], 0ull);   // atomic read
            if (idx_out)
                idx_out[n] = (float)(C_CATS - 1 - (unsigned)(k & 0xffffffffull));
            g_key[n] = 0ull;                               // self-clean for next replay
            g_cnt[n] = 0u;
        }
    }
}

// ---------------------------------------------------------------------------
extern "C" void kernel_launch(void* const* d_in, const int* in_sizes, int n_in,
                              void* d_out, int out_size) {
    const float* x = (const float*)d_in[0];
    const float* w = (const float*)d_in[1];
    float* out = (float*)d_out;

    float* idx_out = (out_size >= N_ROWS * C_CATS + N_ROWS)
                   ? out + (size_t)N_ROWS * C_CATS : nullptr;

    dim3 grid(C_CATS / BN, N_ROWS / BM);   // (8, 16) = 128 blocks
    fused_kernel<<<grid, 256>>>(x, w, out, idx_out);
}